// round 8
// baseline (speedup 1.0000x reference)
#include <cuda_runtime.h>
#include <math.h>
#include <limits.h>

#define B     32
#define D     512
#define M     10000
#define KTOP  5
#define R3    32768
#define EPS   1e-12f

// sim tiling
#define BN    80            // keys per block (125 * 80 = 10000)
#define STHR  160           // 5 warps
#define NDQ   8             // D eighths: 64 floats = 16 float4
#define KROW  16            // key row stride (f4) before skew
#define XROW  20            // x row stride (f4) before skew

#define KS_F4 (BN * KROW + 20)     // 1300
#define XS_F4 (32 * XROW + 8)      // 648
#define SIM_SMEM ((KS_F4 + XS_F4) * 16)

typedef unsigned long long ull;

// -------- device scratch --------
__device__ float g_spart[NDQ][B * M];   // partial dots per d-slice
__device__ float g_knp[NDQ][M];         // partial key norms^2
__device__ float g_rk[M];
__device__ float g_rq[B];
__device__ int   g_topidx[B * KTOP];
__device__ float g_topval[B * KTOP];

// -------- helpers --------
__device__ __forceinline__ void fma2(ull& d, ull a, ull b) {
    asm("fma.rn.f32x2 %0, %1, %2, %0;" : "+l"(d) : "l"(a), "l"(b));
}
__device__ __forceinline__ float2 up2(ull v) {
    float2 f;
    asm("mov.b64 {%0, %1}, %2;" : "=f"(f.x), "=f"(f.y) : "l"(v));
    return f;
}
__device__ __forceinline__ unsigned smem_u32(const void* p) {
    unsigned a;
    asm("{ .reg .u64 t; cvta.to.shared.u64 t, %1; cvt.u32.u64 %0, t; }" : "=r"(a) : "l"(p));
    return a;
}

// ============================================================
// Kernel 1: partial similarity. grid = (125, 8), block = 160.
// Block: 80 keys x 32 b x 64 d. Warp: 32b x 16k. Thread: 4b x 4k.
// launch_bounds(160,4): 4 blocks/SM -> 20 warps/SM.
// ============================================================
__global__ void __launch_bounds__(STHR, 4) k_sim(const float* __restrict__ x,
                                                 const float* __restrict__ keys) {
    extern __shared__ float4 smem[];
    float4* ks4 = smem;              // [80*16 + skew]
    float4* xs4 = smem + KS_F4;      // [32*20 + skew]

    const int tid  = threadIdx.x;
    const int lane = tid & 31;
    const int wid  = tid >> 5;           // 0..4
    const int kgrp = lane & 3;
    const int bgrp = lane >> 2;
    const int m0   = blockIdx.x * BN;
    const int dq   = blockIdx.y;
    const int doff = dq * 16;            // float4 offset into D

    const float4* __restrict__ x4    = (const float4*)x;
    const float4* __restrict__ keys4 = (const float4*)keys;

    // ---- load keys: 80 x 16 f4; 2 keys per warp-row ----
    #pragma unroll
    for (int r = 0; r < 8; ++r) {
        int flat = tid + STHR * r;
        int k    = flat >> 4;
        int d4c  = flat & 15;
        float4 v = keys4[(size_t)(m0 + k) * 128 + doff + d4c];
        float s  = v.x * v.x + v.y * v.y + v.z * v.z + v.w * v.w;
        #pragma unroll
        for (int o = 8; o > 0; o >>= 1) s += __shfl_xor_sync(0xFFFFFFFFu, s, o);
        if ((lane & 15) == 0) g_knp[dq][m0 + k] = s;
        ks4[k * KROW + d4c + (k >> 2)] = v;
    }
    // ---- load x: 32 b x 16 f4, skewed ----
    #pragma unroll
    for (int r = 0; r < 4; ++r) {
        int flat = tid + STHR * r;
        if (flat < 512) {
            int bb  = flat >> 4;
            int d4c = flat & 15;
            xs4[bb * XROW + d4c + (bb >> 2)] = x4[bb * 128 + doff + d4c];
        }
    }
    __syncthreads();

    // ---- compute: 16 d4 steps x (8 LDS.128 + 32 fma2) ----
    ull acc[4][4];
    #pragma unroll
    for (int i = 0; i < 4; ++i)
        #pragma unroll
        for (int j = 0; j < 4; ++j) acc[i][j] = 0ull;

    const int kbase  = wid * 16 + kgrp * 4;
    const float4* kp = ks4 + kbase * KROW + (wid * 4 + kgrp);  // kbase>>2 skew
    const float4* xp = xs4 + bgrp * (4 * XROW + 1);            // bgrp*81

    #pragma unroll
    for (int d4c = 0; d4c < 16; ++d4c) {
        ulonglong2 kv[4];
        #pragma unroll
        for (int j = 0; j < 4; ++j)
            kv[j] = *(const ulonglong2*)(kp + j * KROW + d4c);
        #pragma unroll
        for (int i = 0; i < 4; ++i) {
            ulonglong2 xv = *(const ulonglong2*)(xp + i * XROW + d4c);
            #pragma unroll
            for (int j = 0; j < 4; ++j) {
                fma2(acc[i][j], xv.x, kv[j].x);
                fma2(acc[i][j], xv.y, kv[j].y);
            }
        }
    }

    // ---- epilogue: partial dots ----
    #pragma unroll
    for (int i = 0; i < 4; ++i) {
        int b = bgrp * 4 + i;
        #pragma unroll
        for (int j = 0; j < 4; ++j) {
            float2 p = up2(acc[i][j]);
            g_spart[dq][b * M + m0 + kbase + j] = p.x + p.y;
        }
    }
}

// ============================================================
// Kernel 2: norms. blocks 0..39 -> rk[m]; 40..43 -> rq[b].
// ============================================================
__global__ void __launch_bounds__(256) k_nrm(const float* __restrict__ x) {
    const int bid = blockIdx.x;
    const int tid = threadIdx.x;
    if (bid < 40) {
        int m = bid * 256 + tid;
        if (m < M) {
            float s = 0.f;
            #pragma unroll
            for (int q = 0; q < NDQ; ++q) s += g_knp[q][m];
            g_rk[m] = 1.0f / fmaxf(sqrtf(s), EPS);
        }
    } else {
        int b    = (bid - 40) * 8 + (tid >> 5);
        int lane = tid & 31;
        float s = 0.f;
        #pragma unroll
        for (int c = 0; c < 4; ++c) {
            float4 v = ((const float4*)x)[b * 128 + lane + 32 * c];
            s += v.x * v.x + v.y * v.y + v.z * v.z + v.w * v.w;
        }
        #pragma unroll
        for (int o = 16; o > 0; o >>= 1) s += __shfl_xor_sync(0xFFFFFFFFu, s, o);
        if (lane == 0) g_rq[b] = 1.0f / fmaxf(sqrtf(s), EPS);
    }
}

// ============================================================
// Kernel 3: top-5, float4-vectorized. 32 blocks x 256.
// Tie-break: lower index (matches jax.lax.top_k).
// ============================================================
#define INS5(v, m)                                                                 \
    if ((v) > t4) {                                                                \
        if ((v) > t0)      { t4=t3;x4=x3; t3=t2;x3=x2; t2=t1;x2=x1; t1=t0;x1=x0; t0=(v);x0=(m); } \
        else if ((v) > t1) { t4=t3;x4=x3; t3=t2;x3=x2; t2=t1;x2=x1; t1=(v);x1=(m); }              \
        else if ((v) > t2) { t4=t3;x4=x3; t3=t2;x3=x2; t2=(v);x2=(m); }                            \
        else if ((v) > t3) { t4=t3;x4=x3; t3=(v);x3=(m); }                                         \
        else               { t4=(v);x4=(m); }                                                      \
    }

__global__ void __launch_bounds__(256) k_topk() {
    __shared__ float s_cv[40];
    __shared__ int   s_ci[40];

    const int b    = blockIdx.x;
    const int tid  = threadIdx.x;
    const int w    = tid >> 5;
    const int lane = tid & 31;

    const float4* __restrict__ rk4 = (const float4*)g_rk;

    float t0 = -INFINITY, t1 = -INFINITY, t2 = -INFINITY, t3 = -INFINITY, t4 = -INFINITY;
    int   x0 = INT_MAX, x1 = INT_MAX, x2 = INT_MAX, x3 = INT_MAX, x4 = INT_MAX;

    #pragma unroll 2
    for (int it = 0; it < 10; ++it) {
        int m4 = tid + 256 * it;
        if (m4 < 2500) {
            float4 sum = ((const float4*)(g_spart[0] + b * M))[m4];
            #pragma unroll
            for (int q = 1; q < NDQ; ++q) {
                float4 p = ((const float4*)(g_spart[q] + b * M))[m4];
                sum.x += p.x; sum.y += p.y; sum.z += p.z; sum.w += p.w;
            }
            float4 r = rk4[m4];
            int m = 4 * m4;
            INS5(sum.x * r.x, m)
            INS5(sum.y * r.y, m + 1)
            INS5(sum.z * r.z, m + 2)
            INS5(sum.w * r.w, m + 3)
        }
    }

    #pragma unroll
    for (int kk = 0; kk < 5; ++kk) {
        float bv = t0; int bi = x0;
        #pragma unroll
        for (int o = 16; o > 0; o >>= 1) {
            float ov = __shfl_xor_sync(0xFFFFFFFFu, bv, o);
            int   oi = __shfl_xor_sync(0xFFFFFFFFu, bi, o);
            if (ov > bv || (ov == bv && oi < bi)) { bv = ov; bi = oi; }
        }
        if (x0 == bi) { t0=t1;x0=x1; t1=t2;x1=x2; t2=t3;x2=x3; t3=t4;x3=x4; t4=-INFINITY;x4=INT_MAX; }
        if (lane == 0) { s_cv[w * 5 + kk] = bv; s_ci[w * 5 + kk] = bi; }
    }
    __syncthreads();

    if (w == 0) {
        float rq = g_rq[b];
        float va = s_cv[lane];
        int   ia = s_ci[lane];
        float vb = (lane + 32 < 40) ? s_cv[lane + 32] : -INFINITY;
        int   ib = (lane + 32 < 40) ? s_ci[lane + 32] : INT_MAX;
        if (vb > va || (vb == va && ib < ia)) {
            float tv = va; va = vb; vb = tv;
            int   ti = ia; ia = ib; ib = ti;
        }
        #pragma unroll
        for (int kk = 0; kk < 5; ++kk) {
            float bv = va; int bi = ia;
            #pragma unroll
            for (int o = 16; o > 0; o >>= 1) {
                float ov = __shfl_xor_sync(0xFFFFFFFFu, bv, o);
                int   oi = __shfl_xor_sync(0xFFFFFFFFu, bi, o);
                if (ov > bv || (ov == bv && oi < bi)) { bv = ov; bi = oi; }
            }
            if (ia == bi) { va = vb; ia = ib; vb = -INFINITY; ib = INT_MAX; }
            if (lane == 0) { g_topval[b * KTOP + kk] = bv * rq; g_topidx[b * KTOP + kk] = bi; }
        }
    }
}

// ============================================================
// Kernel 4: gather via pipelined cp.async.bulk ring.
// 320 blocks x 64KB. 8 chunks x 8KB, 4 buffers, lookahead 3.
// Steady state per block: 1 store + up to 3 loads in flight.
// ============================================================
#define GCH   8        // chunks per block
#define GBUF  4        // ring buffers
#define GCB   8192u    // bytes per chunk (2048 floats)

__global__ void __launch_bounds__(256) k_gather(const float* __restrict__ vals,
                                                float* __restrict__ out,
                                                int out_size) {
    __shared__ alignas(128) float buf[GBUF][2048];
    __shared__ alignas(8)  unsigned long long mbar[GBUF];

    const int t = threadIdx.x;

    if (blockIdx.x == 0) {   // idx/vals tail
        const int total = B * KTOP * R3;         // 5242880
        if (out_size >= total + 2 * B * KTOP && t < B * KTOP) {
            out[total + t]            = (float)g_topidx[t];
            out[total + B * KTOP + t] = g_topval[t];
        }
    }

    if (t == 0) {
        const int pair = blockIdx.x >> 1;
        const int half = blockIdx.x & 1;
        const int idx  = g_topidx[pair];
        const float* src = vals + (size_t)idx  * R3 + half * 16384;
        float*       dst = out  + (size_t)pair * R3 + half * 16384;

        unsigned mb[GBUF], bs[GBUF];
        #pragma unroll
        for (int s = 0; s < GBUF; ++s) {
            mb[s] = smem_u32(&mbar[s]);
            bs[s] = smem_u32(buf[s]);
            asm volatile("mbarrier.init.shared.b64 [%0], %1;" :: "r"(mb[s]), "r"(1) : "memory");
        }
        asm volatile("fence.proxy.async.shared::cta;" ::: "memory");

        // prologue: loads for chunks 0..2
        #pragma unroll
        for (int c = 0; c < 3; ++c) {
            asm volatile("mbarrier.arrive.expect_tx.shared.b64 _, [%0], %1;"
                         :: "r"(mb[c]), "r"(GCB) : "memory");
            asm volatile("cp.async.bulk.shared::cluster.global.mbarrier::complete_tx::bytes "
                         "[%0], [%1], %2, [%3];"
                         :: "r"(bs[c]), "l"(src + c * 2048), "r"(GCB), "r"(mb[c]) : "memory");
        }

        #pragma unroll 1
        for (int c = 0; c < GCH; ++c) {
            const int s  = c & (GBUF - 1);
            const unsigned ph = (c >> 2) & 1;

            unsigned done = 0;
            while (!done) {
                asm volatile("{ .reg .pred p; mbarrier.try_wait.parity.shared.b64 p, [%1], %2, 0x989680; "
                             "selp.b32 %0, 1, 0, p; }"
                             : "=r"(done) : "r"(mb[s]), "r"(ph) : "memory");
            }

            asm volatile("cp.async.bulk.global.shared::cta.bulk_group [%0], [%1], %2;"
                         :: "l"(dst + c * 2048), "r"(bs[s]), "r"(GCB) : "memory");
            asm volatile("cp.async.bulk.commit_group;" ::: "memory");

            const int nc = c + 3;
            if (nc < GCH) {
                // store of chunk nc-4 (same buffer) must be done: allow 1 pending (chunk c's)
                asm volatile("cp.async.bulk.wait_group 1;" ::: "memory");
                const int ns = nc & (GBUF - 1);
                asm volatile("mbarrier.arrive.expect_tx.shared.b64 _, [%0], %1;"
                             :: "r"(mb[ns]), "r"(GCB) : "memory");
                asm volatile("cp.async.bulk.shared::cluster.global.mbarrier::complete_tx::bytes "
                             "[%0], [%1], %2, [%3];"
                             :: "r"(bs[ns]), "l"(src + nc * 2048), "r"(GCB), "r"(mb[ns]) : "memory");
            }
        }
        asm volatile("cp.async.bulk.wait_group 0;" ::: "memory");
    }
}

// ============================================================
extern "C" void kernel_launch(void* const* d_in, const int* in_sizes, int n_in,
                              void* d_out, int out_size) {
    const float* x    = (const float*)d_in[0];  // (32, 512)
    const float* keys = (const float*)d_in[1];  // (10000, 512)
    const float* vals = (const float*)d_in[2];  // (10000, 32, 32, 32)

    float* out = (float*)d_out;

    cudaFuncSetAttribute(k_sim, cudaFuncAttributeMaxDynamicSharedMemorySize, SIM_SMEM);

    k_sim<<<dim3(M / BN, NDQ), STHR, SIM_SMEM>>>(x, keys);  // 1000 blocks
    k_nrm<<<44, 256>>>(x);
    k_topk<<<B, 256>>>();
    k_gather<<<B * KTOP * 2, 256>>>(vals, out, out_size);
}

// round 10
// speedup vs baseline: 1.1105x; 1.1105x over previous
#include <cuda_runtime.h>
#include <math.h>
#include <limits.h>

#define B     32
#define D     512
#define M     10000
#define KTOP  5
#define R3    32768
#define EPS   1e-12f

// sim tiling (R5 geometry — measured 19.5us — with norm restructure)
#define BN    80            // keys per block (125 * 80 = 10000)
#define STHR  160           // 5 warps
#define NDQ   4             // D quarters of 128 floats (32 float4)
#define KROW  32            // key row stride (f4) before skew
#define XROW  40            // x row stride (f4) before skew

#define KS_F4 (BN * KROW + 20)
#define XS_F4 (32 * XROW + 8)
#define SIM_SMEM ((KS_F4 + XS_F4) * 16)

typedef unsigned long long ull;

// -------- device scratch --------
__device__ float g_spart[NDQ][B * M];   // partial dots per d-quarter
__device__ float g_knp[NDQ][M];         // partial key norms^2
__device__ float g_rk[M];
__device__ float g_rq[B];
__device__ int   g_topidx[B * KTOP];
__device__ float g_topval[B * KTOP];

// -------- packed f32x2 helpers --------
__device__ __forceinline__ void fma2(ull& d, ull a, ull b) {
    asm("fma.rn.f32x2 %0, %1, %2, %0;" : "+l"(d) : "l"(a), "l"(b));
}
__device__ __forceinline__ float2 up2(ull v) {
    float2 f;
    asm("mov.b64 {%0, %1}, %2;" : "=f"(f.x), "=f"(f.y) : "l"(v));
    return f;
}

// ============================================================
// Kernel 1: partial similarity. grid = (125, 4), block = 160.
// Block: 80 keys x 32 b x 128 d. Warp: 32b x 16k. Thread: 4b x 4k.
// Norms: computed from smem AFTER the fill (no shuffles in the
// load phase -> LDGs batch at full MLP).
// ============================================================
__global__ void __launch_bounds__(STHR, 3) k_sim(const float* __restrict__ x,
                                                 const float* __restrict__ keys) {
    extern __shared__ float4 smem[];
    float4* ks4 = smem;              // [80*32 + skew]
    float4* xs4 = smem + KS_F4;      // [32*40 + skew]

    const int tid  = threadIdx.x;
    const int lane = tid & 31;
    const int wid  = tid >> 5;           // 0..4
    const int kgrp = lane & 3;
    const int bgrp = lane >> 2;
    const int m0   = blockIdx.x * BN;
    const int dq   = blockIdx.y;
    const int doff = dq * 32;

    const float4* __restrict__ x4    = (const float4*)x;
    const float4* __restrict__ keys4 = (const float4*)keys;

    // ---- fill: pure LDG -> STS, no reductions ----
    #pragma unroll
    for (int r = 0; r < 16; ++r) {
        int flat = tid + STHR * r;
        int k    = flat >> 5;
        int d4c  = flat & 31;
        ks4[k * KROW + d4c + (k >> 2)] = keys4[(size_t)(m0 + k) * 128 + doff + d4c];
    }
    #pragma unroll
    for (int r = 0; r < 7; ++r) {
        int flat = tid + STHR * r;
        if (flat < 1024) {
            int bb  = flat >> 5;
            int d4c = flat & 31;
            xs4[bb * XROW + d4c + (bb >> 2)] = x4[bb * 128 + doff + d4c];
        }
    }
    __syncthreads();

    // ---- key norm partial from smem (2 threads per key, staggered) ----
    float np = 0.f;
    {
        const int kn = tid >> 1;             // 0..79
        const int h  = tid & 1;              // half of the 32 f4s
        #pragma unroll
        for (int i = 0; i < 16; ++i) {
            int col = h * 16 + ((i + kn) & 15);
            float4 v = ks4[kn * KROW + col + (kn >> 2)];
            np += v.x * v.x + v.y * v.y + v.z * v.z + v.w * v.w;
        }
    }

    // ---- compute: 32 d4 steps x (8 LDS.128 + 32 fma2) ----
    ull acc[4][4];
    #pragma unroll
    for (int i = 0; i < 4; ++i)
        #pragma unroll
        for (int j = 0; j < 4; ++j) acc[i][j] = 0ull;

    const int kbase  = wid * 16 + kgrp * 4;
    const float4* kp = ks4 + kbase * KROW + (wid * 4 + kgrp);
    const float4* xp = xs4 + bgrp * (4 * XROW + 1);

    #pragma unroll
    for (int d4c = 0; d4c < 32; ++d4c) {
        ulonglong2 kv[4];
        #pragma unroll
        for (int j = 0; j < 4; ++j)
            kv[j] = *(const ulonglong2*)(kp + j * KROW + d4c);
        #pragma unroll
        for (int i = 0; i < 4; ++i) {
            ulonglong2 xv = *(const ulonglong2*)(xp + i * XROW + d4c);
            #pragma unroll
            for (int j = 0; j < 4; ++j) {
                fma2(acc[i][j], xv.x, kv[j].x);
                fma2(acc[i][j], xv.y, kv[j].y);
            }
        }
    }

    // ---- norm combine: adjacent lanes hold the two halves of key tid>>1 ----
    np += __shfl_xor_sync(0xFFFFFFFFu, np, 1);
    if ((tid & 1) == 0) g_knp[dq][m0 + (tid >> 1)] = np;

    // ---- epilogue: partial dots ----
    #pragma unroll
    for (int i = 0; i < 4; ++i) {
        int b = bgrp * 4 + i;
        #pragma unroll
        for (int j = 0; j < 4; ++j) {
            float2 p = up2(acc[i][j]);
            g_spart[dq][b * M + m0 + kbase + j] = p.x + p.y;
        }
    }
}

// ============================================================
// Kernel 2: norms. blocks 0..39 -> rk[m]; 40..43 -> rq[b].
// ============================================================
__global__ void __launch_bounds__(256) k_nrm(const float* __restrict__ x) {
    const int bid = blockIdx.x;
    const int tid = threadIdx.x;
    if (bid < 40) {
        int m = bid * 256 + tid;
        if (m < M) {
            float s = g_knp[0][m] + g_knp[1][m] + g_knp[2][m] + g_knp[3][m];
            g_rk[m] = 1.0f / fmaxf(sqrtf(s), EPS);
        }
    } else {
        int b    = (bid - 40) * 8 + (tid >> 5);
        int lane = tid & 31;
        float s = 0.f;
        #pragma unroll
        for (int c = 0; c < 4; ++c) {
            float4 v = ((const float4*)x)[b * 128 + lane + 32 * c];
            s += v.x * v.x + v.y * v.y + v.z * v.z + v.w * v.w;
        }
        #pragma unroll
        for (int o = 16; o > 0; o >>= 1) s += __shfl_xor_sync(0xFFFFFFFFu, s, o);
        if (lane == 0) g_rq[b] = 1.0f / fmaxf(sqrtf(s), EPS);
    }
}

// ============================================================
// Kernel 3: top-5, float4-vectorized. 32 blocks x 256.
// Tie-break: lower index (matches jax.lax.top_k).
// ============================================================
#define INS5(v, m)                                                                 \
    if ((v) > t4) {                                                                \
        if ((v) > t0)      { t4=t3;x4=x3; t3=t2;x3=x2; t2=t1;x2=x1; t1=t0;x1=x0; t0=(v);x0=(m); } \
        else if ((v) > t1) { t4=t3;x4=x3; t3=t2;x3=x2; t2=t1;x2=x1; t1=(v);x1=(m); }              \
        else if ((v) > t2) { t4=t3;x4=x3; t3=t2;x3=x2; t2=(v);x2=(m); }                            \
        else if ((v) > t3) { t4=t3;x4=x3; t3=(v);x3=(m); }                                         \
        else               { t4=(v);x4=(m); }                                                      \
    }

__global__ void __launch_bounds__(256) k_topk() {
    __shared__ float s_cv[40];
    __shared__ int   s_ci[40];

    const int b    = blockIdx.x;
    const int tid  = threadIdx.x;
    const int w    = tid >> 5;
    const int lane = tid & 31;

    const float4* __restrict__ sp0 = (const float4*)(g_spart[0] + b * M);
    const float4* __restrict__ sp1 = (const float4*)(g_spart[1] + b * M);
    const float4* __restrict__ sp2 = (const float4*)(g_spart[2] + b * M);
    const float4* __restrict__ sp3 = (const float4*)(g_spart[3] + b * M);
    const float4* __restrict__ rk4 = (const float4*)g_rk;

    float t0 = -INFINITY, t1 = -INFINITY, t2 = -INFINITY, t3 = -INFINITY, t4 = -INFINITY;
    int   x0 = INT_MAX, x1 = INT_MAX, x2 = INT_MAX, x3 = INT_MAX, x4 = INT_MAX;

    #pragma unroll 2
    for (int it = 0; it < 10; ++it) {
        int m4 = tid + 256 * it;
        if (m4 < 2500) {
            float4 a = sp0[m4], c = sp1[m4], d = sp2[m4], e = sp3[m4], r = rk4[m4];
            float v0 = (a.x + c.x + d.x + e.x) * r.x;
            float v1 = (a.y + c.y + d.y + e.y) * r.y;
            float v2 = (a.z + c.z + d.z + e.z) * r.z;
            float v3 = (a.w + c.w + d.w + e.w) * r.w;
            int m = 4 * m4;
            INS5(v0, m)
            INS5(v1, m + 1)
            INS5(v2, m + 2)
            INS5(v3, m + 3)
        }
    }

    #pragma unroll
    for (int kk = 0; kk < 5; ++kk) {
        float bv = t0; int bi = x0;
        #pragma unroll
        for (int o = 16; o > 0; o >>= 1) {
            float ov = __shfl_xor_sync(0xFFFFFFFFu, bv, o);
            int   oi = __shfl_xor_sync(0xFFFFFFFFu, bi, o);
            if (ov > bv || (ov == bv && oi < bi)) { bv = ov; bi = oi; }
        }
        if (x0 == bi) { t0=t1;x0=x1; t1=t2;x1=x2; t2=t3;x2=x3; t3=t4;x3=x4; t4=-INFINITY;x4=INT_MAX; }
        if (lane == 0) { s_cv[w * 5 + kk] = bv; s_ci[w * 5 + kk] = bi; }
    }
    __syncthreads();

    if (w == 0) {
        float rq = g_rq[b];
        float va = s_cv[lane];
        int   ia = s_ci[lane];
        float vb = (lane + 32 < 40) ? s_cv[lane + 32] : -INFINITY;
        int   ib = (lane + 32 < 40) ? s_ci[lane + 32] : INT_MAX;
        if (vb > va || (vb == va && ib < ia)) {
            float tv = va; va = vb; vb = tv;
            int   ti = ia; ia = ib; ib = ti;
        }
        #pragma unroll
        for (int kk = 0; kk < 5; ++kk) {
            float bv = va; int bi = ia;
            #pragma unroll
            for (int o = 16; o > 0; o >>= 1) {
                float ov = __shfl_xor_sync(0xFFFFFFFFu, bv, o);
                int   oi = __shfl_xor_sync(0xFFFFFFFFu, bi, o);
                if (ov > bv || (ov == bv && oi < bi)) { bv = ov; bi = oi; }
            }
            if (ia == bi) { va = vb; ia = ib; vb = -INFINITY; ib = INT_MAX; }
            if (lane == 0) { g_topval[b * KTOP + kk] = bv * rq; g_topidx[b * KTOP + kk] = bi; }
        }
    }
}

// ============================================================
// Kernel 4: gather. 640 blocks x 32KB, batched MLP=8,
// streaming (ldcs/stcs) to bypass L2 retention / write-allocate.
// ============================================================
__global__ void __launch_bounds__(256) k_gather(const float* __restrict__ vals,
                                                float* __restrict__ out,
                                                int out_size) {
    const int pair  = blockIdx.x >> 2;   // 0..159
    const int chunk = blockIdx.x & 3;    // 0..3
    const int t     = threadIdx.x;

    const int idx = g_topidx[pair];
    const float4* __restrict__ src = (const float4*)vals + (size_t)idx  * 8192 + chunk * 2048;
    float4*       __restrict__ dst = (float4*)out        + (size_t)pair * 8192 + chunk * 2048;

    float4 tmp[8];
    #pragma unroll
    for (int i = 0; i < 8; ++i) tmp[i] = __ldcs(src + t + 256 * i);
    #pragma unroll
    for (int i = 0; i < 8; ++i) __stcs(dst + t + 256 * i, tmp[i]);

    if (blockIdx.x == 0) {
        const int total = B * KTOP * R3;   // 5242880
        if (out_size >= total + 2 * B * KTOP && t < B * KTOP) {
            out[total + t]            = (float)g_topidx[t];
            out[total + B * KTOP + t] = g_topval[t];
        }
    }
}

// ============================================================
extern "C" void kernel_launch(void* const* d_in, const int* in_sizes, int n_in,
                              void* d_out, int out_size) {
    const float* x    = (const float*)d_in[0];  // (32, 512)
    const float* keys = (const float*)d_in[1];  // (10000, 512)
    const float* vals = (const float*)d_in[2];  // (10000, 32, 32, 32)

    float* out = (float*)d_out;

    cudaFuncSetAttribute(k_sim, cudaFuncAttributeMaxDynamicSharedMemorySize, SIM_SMEM);

    k_sim<<<dim3(M / BN, NDQ), STHR, SIM_SMEM>>>(x, keys);  // 500 blocks
    k_nrm<<<44, 256>>>(x);
    k_topk<<<B, 256>>>();
    k_gather<<<B * KTOP * 4, 256>>>(vals, out, out_size);
}